// round 1
// baseline (speedup 1.0000x reference)
#include <cuda_runtime.h>
#include <math.h>

// Fixed problem shape (from setup_inputs): N=100000, F_IN=128, H=C=64
#define NNODES 100000
#define HD 64

// Scratch (allocation-free: __device__ globals)
__device__ float g_deg[NNODES];          // degree, then dis = rsqrt(deg)
__device__ float g_h[NNODES * HD];       // GEMM output (reused both layers)
__device__ float g_agg[NNODES * HD];     // layer-1 aggregate
__device__ int   g_is64;                 // edge_index dtype flag

__device__ __forceinline__ long long load_edge(const void* ei, long long pos) {
    if (g_is64) return ((const long long*)ei)[pos];
    return (long long)((const int*)ei)[pos];
}

// ---------------------------------------------------------------------------
// init: zero agg + out, deg=1 (self loop), detect index width
// ---------------------------------------------------------------------------
__global__ void k_init(const void* ei, float* out, int N) {
    long long i = (long long)blockIdx.x * 256 + threadIdx.x;
    long long total = (long long)N * HD;
    if (i < total) { g_agg[i] = 0.0f; out[i] = 0.0f; }
    if (i < N) g_deg[i] = 1.0f;
    if (i == 0) {
        const unsigned long long* p = (const unsigned long long*)ei;
        int ok = 1;
        #pragma unroll 4
        for (int j = 0; j < 64; j++)
            if (p[j] >= (unsigned long long)N) ok = 0;
        g_is64 = ok;
    }
}

// ---------------------------------------------------------------------------
// degree over dst (self-loop already counted via init deg=1)
// ---------------------------------------------------------------------------
__global__ void k_degree(const void* ei, long long E) {
    long long e = (long long)blockIdx.x * 256 + threadIdx.x;
    if (e < E) {
        int d = (int)load_edge(ei, E + e);
        atomicAdd(&g_deg[d], 1.0f);
    }
}

__global__ void k_rsqrt(int N) {
    int i = blockIdx.x * 256 + threadIdx.x;
    if (i < N) g_deg[i] = rsqrtf(g_deg[i]);
}

// ---------------------------------------------------------------------------
// GEMM: out[N,64] = act(X[N,K]) @ W[K,64]; act = relu(x + bias) if RELU_IN
// 256 threads/block, 16 rows/block; thread (cg, r) computes cols [4cg,4cg+4)
// of local row r.  W kept in natural [K][64] layout in smem (no transpose,
// no bank conflicts); inner loop is LDS.128-fed FMA.
// ---------------------------------------------------------------------------
template <int K, int RELU_IN>
__global__ void k_gemm(const float* __restrict__ X, const float* __restrict__ W,
                       const float* __restrict__ bias, float* __restrict__ out,
                       int N) {
    __shared__ float Ws[K * 64];
    __shared__ float Xs[16 * K];
    __shared__ float bs[64];
    int tid = threadIdx.x;

    for (int i = tid; i < K * 64; i += 256) Ws[i] = W[i];
    if (RELU_IN && tid < 64) bs[tid] = bias[tid];
    if (RELU_IN) __syncthreads();   // bs ready before Xs load uses it

    int row0 = blockIdx.x * 16;
    for (int i = tid; i < 16 * K; i += 256) {
        int r = i / K, c = i % K;
        int gr = row0 + r;
        float v = (gr < N) ? X[(long long)gr * K + c] : 0.0f;
        if (RELU_IN) v = fmaxf(v + bs[c], 0.0f);
        Xs[i] = v;
    }
    __syncthreads();

    int cg = tid & 15;
    int r  = tid >> 4;
    float4 acc = make_float4(0.f, 0.f, 0.f, 0.f);
    const float4* Ws4 = (const float4*)Ws;
    const float4* Xr4 = (const float4*)(Xs + r * K);

    #pragma unroll
    for (int k4 = 0; k4 < K / 4; k4++) {
        float4 xv = Xr4[k4];
        float4 w;
        w = Ws4[(4 * k4 + 0) * 16 + cg];
        acc.x += xv.x * w.x; acc.y += xv.x * w.y; acc.z += xv.x * w.z; acc.w += xv.x * w.w;
        w = Ws4[(4 * k4 + 1) * 16 + cg];
        acc.x += xv.y * w.x; acc.y += xv.y * w.y; acc.z += xv.y * w.z; acc.w += xv.y * w.w;
        w = Ws4[(4 * k4 + 2) * 16 + cg];
        acc.x += xv.z * w.x; acc.y += xv.z * w.y; acc.z += xv.z * w.z; acc.w += xv.z * w.w;
        w = Ws4[(4 * k4 + 3) * 16 + cg];
        acc.x += xv.w * w.x; acc.y += xv.w * w.y; acc.z += xv.w * w.z; acc.w += xv.w * w.w;
    }
    int gr = row0 + r;
    if (gr < N) ((float4*)(out + (long long)gr * 64))[cg] = acc;
}

// ---------------------------------------------------------------------------
// Scatter: agg[dst] += h[src] * dis[src]*dis[dst], incl. self-loops.
// 16 threads per message, each owns one float4 chunk (coalesced 256B
// gather + coalesced red.global.add.v4.f32).
// ---------------------------------------------------------------------------
__global__ void k_scatter(const float* __restrict__ h, float* __restrict__ agg,
                          const void* ei, long long E, int N) {
    long long tid = (long long)blockIdx.x * 256 + threadIdx.x;
    long long tot = (E + (long long)N) * 16;
    if (tid >= tot) return;
    long long e = tid >> 4;
    int k = (int)(tid & 15);
    int s, d;
    if (e < E) {
        s = (int)load_edge(ei, e);
        d = (int)load_edge(ei, E + e);
    } else {
        s = d = (int)(e - E);
    }
    float nrm = g_deg[s] * g_deg[d];
    float4 v = ((const float4*)(h + (long long)s * 64))[k];
    v.x *= nrm; v.y *= nrm; v.z *= nrm; v.w *= nrm;
    float* p = agg + (long long)d * 64 + (long long)k * 4;
    asm volatile("red.global.add.v4.f32 [%0], {%1, %2, %3, %4};"
                 :: "l"(p), "f"(v.x), "f"(v.y), "f"(v.z), "f"(v.w)
                 : "memory");
}

// ---------------------------------------------------------------------------
// log_softmax over 64 classes with bias b2 folded in; one warp per row
// ---------------------------------------------------------------------------
__global__ void k_logsoftmax(float* __restrict__ out, const float* __restrict__ b2,
                             int N) {
    int row = blockIdx.x * 8 + threadIdx.y;
    if (row >= N) return;
    int lane = threadIdx.x;
    float* rp = out + (long long)row * 64;
    float v0 = rp[lane]      + b2[lane];
    float v1 = rp[lane + 32] + b2[lane + 32];
    float m = fmaxf(v0, v1);
    #pragma unroll
    for (int o = 16; o > 0; o >>= 1) m = fmaxf(m, __shfl_xor_sync(0xffffffffu, m, o));
    float s = expf(v0 - m) + expf(v1 - m);
    #pragma unroll
    for (int o = 16; o > 0; o >>= 1) s += __shfl_xor_sync(0xffffffffu, s, o);
    float lse = m + logf(s);
    rp[lane]      = v0 - lse;
    rp[lane + 32] = v1 - lse;
}

// ---------------------------------------------------------------------------
extern "C" void kernel_launch(void* const* d_in, const int* in_sizes, int n_in,
                              void* d_out, int out_size) {
    const float* x  = (const float*)d_in[0];
    const void*  ei = d_in[1];
    const float* W1 = (const float*)d_in[2];
    const float* b1 = (const float*)d_in[3];
    const float* W2 = (const float*)d_in[4];
    const float* b2 = (const float*)d_in[5];
    float* out = (float*)d_out;

    int N = in_sizes[0] / 128;          // 100000
    long long E = (long long)in_sizes[1] / 2;  // 1600000

    float *ph, *pagg;
    cudaGetSymbolAddress((void**)&ph, g_h);
    cudaGetSymbolAddress((void**)&pagg, g_agg);

    long long NH = (long long)N * HD;
    int bInit = (int)((NH + 255) / 256);
    int bDeg  = (int)((E + 255) / 256);
    int bN    = (N + 255) / 256;
    int bGemm = (N + 15) / 16;
    long long scat = (E + (long long)N) * 16;
    int bScat = (int)((scat + 255) / 256);

    k_init<<<bInit, 256>>>(ei, out, N);
    k_degree<<<bDeg, 256>>>(ei, E);
    k_rsqrt<<<bN, 256>>>(N);

    // layer 1: h = x @ W1 ; agg1 = scatter(h)
    k_gemm<128, 0><<<bGemm, 256>>>(x, W1, nullptr, ph, N);
    k_scatter<<<bScat, 256>>>(ph, pagg, ei, E, N);

    // layer 2: h2 = relu(agg1 + b1) @ W2 ; out = scatter(h2)
    k_gemm<64, 1><<<bGemm, 256>>>(pagg, W2, b1, ph, N);
    k_scatter<<<bScat, 256>>>(ph, out, ei, E, N);

    // out = log_softmax(out + b2)
    dim3 lsBlock(32, 8);
    k_logsoftmax<<<(N + 7) / 8, lsBlock>>>(out, b2, N);
}

// round 2
// speedup vs baseline: 2.0783x; 2.0783x over previous
#include <cuda_runtime.h>
#include <math.h>

// Fixed problem shape (from setup_inputs): N=100000, E=1600000, F_IN=128, H=C=64
#define NNODES 100000
#define HD 64
#define MSGMAX 1800000   // E + N with headroom

// Scratch (allocation-free: __device__ globals)
__device__ float  g_deg[NNODES];            // degree (raw counts)
__device__ float  g_h[NNODES * HD];         // GEMM output (reused both layers)
__device__ float  g_agg[NNODES * HD];       // layer-1 aggregate
__device__ float4 g_msg[MSGMAX];            // packed {src, dst, norm, -} per message
__device__ int    g_is64;                   // edge_index dtype flag

__device__ __forceinline__ long long load_edge(const void* ei, long long pos) {
    if (g_is64) return ((const long long*)ei)[pos];
    return (long long)((const int*)ei)[pos];
}

// ---------------------------------------------------------------------------
// init: zero agg + out, deg=1 (self loop), detect index width
// ---------------------------------------------------------------------------
__global__ void k_init(const void* ei, float* out, int N) {
    long long i = (long long)blockIdx.x * 256 + threadIdx.x;
    long long total = (long long)N * HD;
    if (i < total) { g_agg[i] = 0.0f; out[i] = 0.0f; }
    if (i < N) g_deg[i] = 1.0f;
    if (i == 0) {
        const unsigned long long* p = (const unsigned long long*)ei;
        int ok = 1;
        #pragma unroll 4
        for (int j = 0; j < 64; j++)
            if (p[j] >= (unsigned long long)N) ok = 0;
        g_is64 = ok;
    }
}

// ---------------------------------------------------------------------------
// degree over dst (self-loop already counted via init deg=1)
// ---------------------------------------------------------------------------
__global__ void k_degree(const void* ei, long long E) {
    long long e = (long long)blockIdx.x * 256 + threadIdx.x;
    if (e < E) {
        int d = (int)load_edge(ei, E + e);
        atomicAdd(&g_deg[d], 1.0f);
    }
}

// ---------------------------------------------------------------------------
// prep: pack {src, dst, rsqrt(deg[s])*rsqrt(deg[d])} per message (edges then
// self-loops). Built once, consumed by BOTH scatter layers.
// ---------------------------------------------------------------------------
__global__ void k_prep(const void* ei, long long E, int N) {
    long long e = (long long)blockIdx.x * 256 + threadIdx.x;
    long long M = E + (long long)N;
    if (e >= M) return;
    int s, d;
    if (e < E) {
        s = (int)load_edge(ei, e);
        d = (int)load_edge(ei, E + e);
    } else {
        s = d = (int)(e - E);
    }
    float nrm = rsqrtf(g_deg[s]) * rsqrtf(g_deg[d]);
    g_msg[e] = make_float4(__int_as_float(s), __int_as_float(d), nrm, 0.0f);
}

// ---------------------------------------------------------------------------
// GEMM: out[N,64] = act(X[N,K]) @ W[K,64]; act = relu(x + bias) if RELU_IN.
// CTA tile 128 rows x 64 cols, 256 threads, thread tile 8 rows x 4 cols.
// K tiled by 32; X row-major in smem (stride 36 pad), W tile [32][64].
// Per 4-k chunk: 12 LDS.128 per 128 scalar FMAs.
// ---------------------------------------------------------------------------
template <int K, int RELU_IN>
__global__ __launch_bounds__(256, 2)
void k_gemm(const float* __restrict__ X, const float* __restrict__ W,
            const float* __restrict__ bias, float* __restrict__ out, int N) {
    const int KT = 32;          // K tile
    const int KS = 36;          // padded X smem stride (floats)
    __shared__ float Ws[KT * 64];       // 8 KB
    __shared__ float Xs[128 * KS];      // 18 KB
    __shared__ float bs[64];

    int tid = threadIdx.x;
    int cg = tid & 15;          // column group: 4 cols
    int rg = tid >> 4;          // row group: 8 rows
    int row0 = blockIdx.x * 128;

    if (RELU_IN && tid < 64) bs[tid] = bias[tid];

    float4 acc[8];
    #pragma unroll
    for (int j = 0; j < 8; j++) acc[j] = make_float4(0.f, 0.f, 0.f, 0.f);

    for (int kt = 0; kt < K; kt += KT) {
        __syncthreads();   // also orders bs before first X-tile use
        // load W tile [KT][64]: 512 float4, 2 per thread (contiguous)
        {
            const float4* Wg = (const float4*)W + (long long)kt * 16;
            float4* Wt = (float4*)Ws;
            Wt[tid]       = Wg[tid];
            Wt[tid + 256] = Wg[tid + 256];
        }
        // load X tile [128][KT]: 1024 float4, 4 per thread, coalesced in k
        #pragma unroll
        for (int i = 0; i < 4; i++) {
            int idx = i * 256 + tid;      // 0..1023
            int r  = idx >> 3;
            int kq = idx & 7;
            int gr = row0 + r;
            float4 v = make_float4(0.f, 0.f, 0.f, 0.f);
            if (gr < N)
                v = *(const float4*)(X + (long long)gr * K + kt + kq * 4);
            if (RELU_IN) {
                int kb = kt + kq * 4;
                v.x = fmaxf(v.x + bs[kb + 0], 0.f);
                v.y = fmaxf(v.y + bs[kb + 1], 0.f);
                v.z = fmaxf(v.z + bs[kb + 2], 0.f);
                v.w = fmaxf(v.w + bs[kb + 3], 0.f);
            }
            *(float4*)(Xs + r * KS + kq * 4) = v;
        }
        __syncthreads();

        const float4* Ws4 = (const float4*)Ws;
        #pragma unroll
        for (int k4 = 0; k4 < KT / 4; k4++) {
            float4 w0 = Ws4[(k4 * 4 + 0) * 16 + cg];
            float4 w1 = Ws4[(k4 * 4 + 1) * 16 + cg];
            float4 w2 = Ws4[(k4 * 4 + 2) * 16 + cg];
            float4 w3 = Ws4[(k4 * 4 + 3) * 16 + cg];
            #pragma unroll
            for (int j = 0; j < 8; j++) {
                float4 xv = *(const float4*)(Xs + (rg * 8 + j) * KS + k4 * 4);
                acc[j].x += xv.x * w0.x + xv.y * w1.x + xv.z * w2.x + xv.w * w3.x;
                acc[j].y += xv.x * w0.y + xv.y * w1.y + xv.z * w2.y + xv.w * w3.y;
                acc[j].z += xv.x * w0.z + xv.y * w1.z + xv.z * w2.z + xv.w * w3.z;
                acc[j].w += xv.x * w0.w + xv.y * w1.w + xv.z * w2.w + xv.w * w3.w;
            }
        }
    }

    #pragma unroll
    for (int j = 0; j < 8; j++) {
        int gr = row0 + rg * 8 + j;
        if (gr < N)
            ((float4*)(out + (long long)gr * 64))[cg] = acc[j];
    }
}

// ---------------------------------------------------------------------------
// Scatter: agg[dst] += h[src] * norm, incl. self-loops, from packed g_msg.
// 16 threads per message, each owns one float4 chunk (coalesced 256B gather
// + coalesced red.global.add.v4.f32; msg load is a 16-way broadcast).
// ---------------------------------------------------------------------------
__global__ void k_scatter(const float* __restrict__ h, float* __restrict__ agg,
                          long long M) {
    long long tid = (long long)blockIdx.x * 256 + threadIdx.x;
    if (tid >= M * 16) return;
    long long e = tid >> 4;
    int k = (int)(tid & 15);
    float4 m = g_msg[e];
    int s = __float_as_int(m.x);
    int d = __float_as_int(m.y);
    float nrm = m.z;
    float4 v = ((const float4*)(h + (long long)s * 64))[k];
    v.x *= nrm; v.y *= nrm; v.z *= nrm; v.w *= nrm;
    float* p = agg + (long long)d * 64 + (long long)k * 4;
    asm volatile("red.global.add.v4.f32 [%0], {%1, %2, %3, %4};"
                 :: "l"(p), "f"(v.x), "f"(v.y), "f"(v.z), "f"(v.w)
                 : "memory");
}

// ---------------------------------------------------------------------------
// log_softmax over 64 classes with bias b2 folded in; one warp per row
// ---------------------------------------------------------------------------
__global__ void k_logsoftmax(float* __restrict__ out, const float* __restrict__ b2,
                             int N) {
    int row = blockIdx.x * 8 + threadIdx.y;
    if (row >= N) return;
    int lane = threadIdx.x;
    float* rp = out + (long long)row * 64;
    float v0 = rp[lane]      + b2[lane];
    float v1 = rp[lane + 32] + b2[lane + 32];
    float m = fmaxf(v0, v1);
    #pragma unroll
    for (int o = 16; o > 0; o >>= 1) m = fmaxf(m, __shfl_xor_sync(0xffffffffu, m, o));
    float s = expf(v0 - m) + expf(v1 - m);
    #pragma unroll
    for (int o = 16; o > 0; o >>= 1) s += __shfl_xor_sync(0xffffffffu, s, o);
    float lse = m + logf(s);
    rp[lane]      = v0 - lse;
    rp[lane + 32] = v1 - lse;
}

// ---------------------------------------------------------------------------
extern "C" void kernel_launch(void* const* d_in, const int* in_sizes, int n_in,
                              void* d_out, int out_size) {
    const float* x  = (const float*)d_in[0];
    const void*  ei = d_in[1];
    const float* W1 = (const float*)d_in[2];
    const float* b1 = (const float*)d_in[3];
    const float* W2 = (const float*)d_in[4];
    const float* b2 = (const float*)d_in[5];
    float* out = (float*)d_out;

    int N = in_sizes[0] / 128;                 // 100000
    long long E = (long long)in_sizes[1] / 2;  // 1600000
    long long M = E + (long long)N;

    float *ph, *pagg;
    cudaGetSymbolAddress((void**)&ph, g_h);
    cudaGetSymbolAddress((void**)&pagg, g_agg);

    long long NH = (long long)N * HD;
    int bInit = (int)((NH + 255) / 256);
    int bDeg  = (int)((E + 255) / 256);
    int bMsg  = (int)((M + 255) / 256);
    int bGemm = (N + 127) / 128;
    int bScat = (int)((M * 16 + 255) / 256);

    k_init<<<bInit, 256>>>(ei, out, N);
    k_degree<<<bDeg, 256>>>(ei, E);
    k_prep<<<bMsg, 256>>>(ei, E, N);

    // layer 1: h = x @ W1 ; agg1 = scatter(h)
    k_gemm<128, 0><<<bGemm, 256>>>(x, W1, nullptr, ph, N);
    k_scatter<<<bScat, 256>>>(ph, pagg, M);

    // layer 2: h2 = relu(agg1 + b1) @ W2 ; out = scatter(h2)
    k_gemm<64, 1><<<bGemm, 256>>>(pagg, W2, b1, ph, N);
    k_scatter<<<bScat, 256>>>(ph, out, M);

    // out = log_softmax(out + b2)
    dim3 lsBlock(32, 8);
    k_logsoftmax<<<(N + 7) / 8, lsBlock>>>(out, b2, N);
}

// round 3
// speedup vs baseline: 3.2937x; 1.5847x over previous
#include <cuda_runtime.h>
#include <math.h>

// Fixed problem shape (from setup_inputs): N=100000, E=1600000, F_IN=128, H=C=64
#define NNODES 100000
#define HD 64
#define MSGMAX 1800000   // E + N with headroom

// Scratch (allocation-free: __device__ globals)
__device__ int    g_cnt[NNODES];            // per-dst message count (incl. self-loop)
__device__ int    g_off[NNODES + 1];        // CSR offsets
__device__ int    g_cur[NNODES];            // placement cursors
__device__ int    g_bsum[512];              // block sums for scan
__device__ int    g_boff[512];              // block offsets for scan
__device__ float2 g_rec[MSGMAX];            // per-message {src_bits, norm}
__device__ float  g_h[NNODES * HD];         // GEMM output (reused both layers)
__device__ float  g_agg[NNODES * HD];       // layer-1 aggregate
__device__ int    g_is64;                   // edge_index dtype flag

__device__ __forceinline__ long long load_edge(const void* ei, long long pos) {
    if (g_is64) return ((const long long*)ei)[pos];
    return (long long)((const int*)ei)[pos];
}

// ---------------------------------------------------------------------------
// init: cnt = 1 (self loop), detect index width
// ---------------------------------------------------------------------------
__global__ void k_init(const void* ei, int N) {
    int i = blockIdx.x * 256 + threadIdx.x;
    if (i < N) g_cnt[i] = 1;
    if (i == 0) {
        const unsigned long long* p = (const unsigned long long*)ei;
        int ok = 1;
        #pragma unroll 4
        for (int j = 0; j < 64; j++)
            if (p[j] >= (unsigned long long)N) ok = 0;
        g_is64 = ok;
    }
}

// ---------------------------------------------------------------------------
// degree count over dst
// ---------------------------------------------------------------------------
__global__ void k_count(const void* ei, long long E) {
    long long e = (long long)blockIdx.x * 256 + threadIdx.x;
    if (e < E) {
        int d = (int)load_edge(ei, E + e);
        atomicAdd(&g_cnt[d], 1);
    }
}

// ---------------------------------------------------------------------------
// 3-phase exclusive scan of g_cnt -> g_off  (N <= 131072: <=512 blocks of 256)
// ---------------------------------------------------------------------------
__global__ void k_scan1(int N) {
    __shared__ int s[256];
    int i = blockIdx.x * 256 + threadIdx.x;
    int v = (i < N) ? g_cnt[i] : 0;
    s[threadIdx.x] = v;
    __syncthreads();
    #pragma unroll
    for (int o = 128; o > 0; o >>= 1) {
        if (threadIdx.x < o) s[threadIdx.x] += s[threadIdx.x + o];
        __syncthreads();
    }
    if (threadIdx.x == 0) g_bsum[blockIdx.x] = s[0];
}

__global__ void k_scan2(int nb) {
    __shared__ int s[512];
    int t = threadIdx.x;
    int v = (t < nb) ? g_bsum[t] : 0;
    s[t] = v;
    __syncthreads();
    #pragma unroll
    for (int o = 1; o < 512; o <<= 1) {
        int tv = (t >= o) ? s[t - o] : 0;
        __syncthreads();
        s[t] += tv;
        __syncthreads();
    }
    if (t < nb) g_boff[t] = s[t] - v;   // exclusive
}

__global__ void k_scan3(int N) {
    __shared__ int s[256];
    int i = blockIdx.x * 256 + threadIdx.x;
    int v = (i < N) ? g_cnt[i] : 0;
    s[threadIdx.x] = v;
    __syncthreads();
    #pragma unroll
    for (int o = 1; o < 256; o <<= 1) {
        int tv = (threadIdx.x >= o) ? s[threadIdx.x - o] : 0;
        __syncthreads();
        s[threadIdx.x] += tv;
        __syncthreads();
    }
    if (i < N) {
        int off = g_boff[blockIdx.x] + s[threadIdx.x] - v;  // exclusive
        g_off[i] = off;
        g_cur[i] = off;
        if (i == N - 1) g_off[N] = off + v;
    }
}

// ---------------------------------------------------------------------------
// place: bucket message records {src, rsqrt(deg_s*deg_d)} by dst
// ---------------------------------------------------------------------------
__global__ void k_place(const void* ei, long long E, int N) {
    long long e = (long long)blockIdx.x * 256 + threadIdx.x;
    long long M = E + (long long)N;
    if (e >= M) return;
    int s, d;
    if (e < E) {
        s = (int)load_edge(ei, e);
        d = (int)load_edge(ei, E + e);
    } else {
        s = d = (int)(e - E);
    }
    float nrm = rsqrtf((float)(g_cnt[s] * g_cnt[d]));
    int pos = atomicAdd(&g_cur[d], 1);
    g_rec[pos] = make_float2(__int_as_float(s), nrm);
}

// ---------------------------------------------------------------------------
// GEMM: out[N,64] = act(X[N,K]) @ W[K,64]; act = relu(x + bias) if RELU_IN.
// CTA tile 128x64, 256 threads, thread tile 8x4, K tiled by 32.
// ---------------------------------------------------------------------------
template <int K, int RELU_IN>
__global__ __launch_bounds__(256, 2)
void k_gemm(const float* __restrict__ X, const float* __restrict__ W,
            const float* __restrict__ bias, float* __restrict__ out, int N) {
    const int KT = 32;
    const int KS = 36;
    __shared__ float Ws[KT * 64];
    __shared__ float Xs[128 * KS];
    __shared__ float bs[64];

    int tid = threadIdx.x;
    int cg = tid & 15;
    int rg = tid >> 4;
    int row0 = blockIdx.x * 128;

    if (RELU_IN && tid < 64) bs[tid] = bias[tid];

    float4 acc[8];
    #pragma unroll
    for (int j = 0; j < 8; j++) acc[j] = make_float4(0.f, 0.f, 0.f, 0.f);

    for (int kt = 0; kt < K; kt += KT) {
        __syncthreads();
        {
            const float4* Wg = (const float4*)W + (long long)kt * 16;
            float4* Wt = (float4*)Ws;
            Wt[tid]       = Wg[tid];
            Wt[tid + 256] = Wg[tid + 256];
        }
        #pragma unroll
        for (int i = 0; i < 4; i++) {
            int idx = i * 256 + tid;
            int r  = idx >> 3;
            int kq = idx & 7;
            int gr = row0 + r;
            float4 v = make_float4(0.f, 0.f, 0.f, 0.f);
            if (gr < N)
                v = *(const float4*)(X + (long long)gr * K + kt + kq * 4);
            if (RELU_IN) {
                int kb = kt + kq * 4;
                v.x = fmaxf(v.x + bs[kb + 0], 0.f);
                v.y = fmaxf(v.y + bs[kb + 1], 0.f);
                v.z = fmaxf(v.z + bs[kb + 2], 0.f);
                v.w = fmaxf(v.w + bs[kb + 3], 0.f);
            }
            *(float4*)(Xs + r * KS + kq * 4) = v;
        }
        __syncthreads();

        const float4* Ws4 = (const float4*)Ws;
        #pragma unroll
        for (int k4 = 0; k4 < KT / 4; k4++) {
            float4 w0 = Ws4[(k4 * 4 + 0) * 16 + cg];
            float4 w1 = Ws4[(k4 * 4 + 1) * 16 + cg];
            float4 w2 = Ws4[(k4 * 4 + 2) * 16 + cg];
            float4 w3 = Ws4[(k4 * 4 + 3) * 16 + cg];
            #pragma unroll
            for (int j = 0; j < 8; j++) {
                float4 xv = *(const float4*)(Xs + (rg * 8 + j) * KS + k4 * 4);
                acc[j].x += xv.x * w0.x + xv.y * w1.x + xv.z * w2.x + xv.w * w3.x;
                acc[j].y += xv.x * w0.y + xv.y * w1.y + xv.z * w2.y + xv.w * w3.y;
                acc[j].z += xv.x * w0.z + xv.y * w1.z + xv.z * w2.z + xv.w * w3.z;
                acc[j].w += xv.x * w0.w + xv.y * w1.w + xv.z * w2.w + xv.w * w3.w;
            }
        }
    }

    #pragma unroll
    for (int j = 0; j < 8; j++) {
        int gr = row0 + rg * 8 + j;
        if (gr < N)
            ((float4*)(out + (long long)gr * 64))[cg] = acc[j];
    }
}

// ---------------------------------------------------------------------------
// Aggregate: out[n] = sum over CSR bucket of h[src]*norm.  Warp per node;
// lanes 0-15 / 16-31 process alternating records, chunk k = lane&15.
// EPI==1: fuse +b2 and log_softmax, write final output.
// ---------------------------------------------------------------------------
template <int EPI>
__global__ void k_agg(const float* __restrict__ h, float* __restrict__ out,
                      const float* __restrict__ bias, int N) {
    int node = blockIdx.x * 8 + (threadIdx.x >> 5);
    if (node >= N) return;
    int lane = threadIdx.x & 31;
    int k = lane & 15;
    int half = lane >> 4;
    int beg = g_off[node];
    int end = g_off[node + 1];

    float4 acc = make_float4(0.f, 0.f, 0.f, 0.f);
    #pragma unroll 2
    for (int j = beg + half; j < end; j += 2) {
        float2 r = g_rec[j];
        int s = __float_as_int(r.x);
        float4 v = __ldg((const float4*)(h + (long long)s * 64) + k);
        acc.x += v.x * r.y;
        acc.y += v.y * r.y;
        acc.z += v.z * r.y;
        acc.w += v.w * r.y;
    }
    // combine the two halves (per-k sums end up duplicated in both halves)
    acc.x += __shfl_xor_sync(0xffffffffu, acc.x, 16);
    acc.y += __shfl_xor_sync(0xffffffffu, acc.y, 16);
    acc.z += __shfl_xor_sync(0xffffffffu, acc.z, 16);
    acc.w += __shfl_xor_sync(0xffffffffu, acc.w, 16);

    if (EPI == 0) {
        if (half == 0)
            ((float4*)(out + (long long)node * 64))[k] = acc;
    } else {
        float4 b = ((const float4*)bias)[k];
        acc.x += b.x; acc.y += b.y; acc.z += b.z; acc.w += b.w;
        float m = fmaxf(fmaxf(acc.x, acc.y), fmaxf(acc.z, acc.w));
        #pragma unroll
        for (int o = 16; o > 0; o >>= 1)
            m = fmaxf(m, __shfl_xor_sync(0xffffffffu, m, o));
        float s = expf(acc.x - m) + expf(acc.y - m) + expf(acc.z - m) + expf(acc.w - m);
        #pragma unroll
        for (int o = 16; o > 0; o >>= 1)
            s += __shfl_xor_sync(0xffffffffu, s, o);
        // 32-lane sum double-counts (k duplicated across halves) -> halve
        float lse = m + logf(s * 0.5f);
        if (half == 0) {
            float4 r = make_float4(acc.x - lse, acc.y - lse, acc.z - lse, acc.w - lse);
            ((float4*)(out + (long long)node * 64))[k] = r;
        }
    }
}

// ---------------------------------------------------------------------------
extern "C" void kernel_launch(void* const* d_in, const int* in_sizes, int n_in,
                              void* d_out, int out_size) {
    const float* x  = (const float*)d_in[0];
    const void*  ei = d_in[1];
    const float* W1 = (const float*)d_in[2];
    const float* b1 = (const float*)d_in[3];
    const float* W2 = (const float*)d_in[4];
    const float* b2 = (const float*)d_in[5];
    float* out = (float*)d_out;

    int N = in_sizes[0] / 128;                 // 100000
    long long E = (long long)in_sizes[1] / 2;  // 1600000
    long long M = E + (long long)N;

    float *ph, *pagg;
    cudaGetSymbolAddress((void**)&ph, g_h);
    cudaGetSymbolAddress((void**)&pagg, g_agg);

    int bN    = (N + 255) / 256;
    int bDeg  = (int)((E + 255) / 256);
    int bMsg  = (int)((M + 255) / 256);
    int bGemm = (N + 127) / 128;
    int bAgg  = (N + 7) / 8;

    k_init<<<bN, 256>>>(ei, N);
    k_count<<<bDeg, 256>>>(ei, E);
    k_scan1<<<bN, 256>>>(N);
    k_scan2<<<1, 512>>>(bN);
    k_scan3<<<bN, 256>>>(N);
    k_place<<<bMsg, 256>>>(ei, E, N);

    // layer 1: h = x @ W1 ; agg1 = aggregate(h)
    k_gemm<128, 0><<<bGemm, 256>>>(x, W1, nullptr, ph, N);
    k_agg<0><<<bAgg, 256>>>(ph, pagg, nullptr, N);

    // layer 2: h2 = relu(agg1 + b1) @ W2 ; out = log_softmax(aggregate(h2) + b2)
    k_gemm<64, 1><<<bGemm, 256>>>(pagg, W2, b1, ph, N);
    k_agg<1><<<bAgg, 256>>>(ph, out, b2, N);
}

// round 4
// speedup vs baseline: 3.3703x; 1.0233x over previous
#include <cuda_runtime.h>
#include <math.h>

// Fixed problem shape (from setup_inputs): N=100000, E=1600000, F_IN=128, H=C=64
#define NNODES 100000
#define HD 64
#define MSGMAX 1800000   // E + N with headroom

// Scratch (allocation-free: __device__ globals)
__device__ int    g_cnt[NNODES];            // per-dst message count (incl. self-loop)
__device__ int    g_off[NNODES + 1];        // CSR offsets
__device__ int    g_cur[NNODES];            // placement cursors
__device__ int    g_bsum[512];              // block sums for scan
__device__ int    g_boff[512];              // block offsets for scan
__device__ float2 g_rec[MSGMAX];            // per-message {src_bits, norm}
__device__ float  g_h[NNODES * HD];         // GEMM output (reused both layers)
__device__ float  g_agg[NNODES * HD];       // layer-1 aggregate
__device__ int    g_is64;                   // edge_index dtype flag

__device__ __forceinline__ long long load_edge(const void* ei, long long pos) {
    if (g_is64) return ((const long long*)ei)[pos];
    return (long long)((const int*)ei)[pos];
}

__device__ __forceinline__ void ffma2(unsigned long long& d, unsigned long long a,
                                      unsigned long long b) {
    asm("fma.rn.f32x2 %0, %1, %2, %0;" : "+l"(d) : "l"(a), "l"(b));
}

// ---------------------------------------------------------------------------
// init: cnt = 1 (self loop), detect index width
// ---------------------------------------------------------------------------
__global__ void k_init(const void* ei, int N) {
    int i = blockIdx.x * 256 + threadIdx.x;
    if (i < N) g_cnt[i] = 1;
    if (i == 0) {
        const unsigned long long* p = (const unsigned long long*)ei;
        int ok = 1;
        #pragma unroll 4
        for (int j = 0; j < 64; j++)
            if (p[j] >= (unsigned long long)N) ok = 0;
        g_is64 = ok;
    }
}

// ---------------------------------------------------------------------------
// degree count over dst
// ---------------------------------------------------------------------------
__global__ void k_count(const void* ei, long long E) {
    long long e = (long long)blockIdx.x * 256 + threadIdx.x;
    if (e < E) {
        int d = (int)load_edge(ei, E + e);
        atomicAdd(&g_cnt[d], 1);
    }
}

// ---------------------------------------------------------------------------
// 3-phase exclusive scan of g_cnt -> g_off  (N <= 131072: <=512 blocks of 256)
// ---------------------------------------------------------------------------
__global__ void k_scan1(int N) {
    __shared__ int s[256];
    int i = blockIdx.x * 256 + threadIdx.x;
    int v = (i < N) ? g_cnt[i] : 0;
    s[threadIdx.x] = v;
    __syncthreads();
    #pragma unroll
    for (int o = 128; o > 0; o >>= 1) {
        if (threadIdx.x < o) s[threadIdx.x] += s[threadIdx.x + o];
        __syncthreads();
    }
    if (threadIdx.x == 0) g_bsum[blockIdx.x] = s[0];
}

// warp-shuffle scan of up to 512 block sums (16 warps)
__global__ void k_scan2(int nb) {
    __shared__ int wsum[16];
    int t = threadIdx.x;
    int lane = t & 31;
    int w = t >> 5;
    int v = (t < nb) ? g_bsum[t] : 0;
    int x = v;
    #pragma unroll
    for (int o = 1; o < 32; o <<= 1) {
        int y = __shfl_up_sync(0xffffffffu, x, o);
        if (lane >= o) x += y;
    }
    if (lane == 31) wsum[w] = x;
    __syncthreads();
    if (w == 0) {
        int ws = (lane < 16) ? wsum[lane] : 0;
        #pragma unroll
        for (int o = 1; o < 16; o <<= 1) {
            int y = __shfl_up_sync(0xffffffffu, ws, o);
            if (lane >= o) ws += y;
        }
        if (lane < 16) wsum[lane] = ws;
    }
    __syncthreads();
    int base = (w > 0) ? wsum[w - 1] : 0;
    if (t < nb) g_boff[t] = base + x - v;   // exclusive
}

__global__ void k_scan3(int N) {
    __shared__ int s[256];
    int i = blockIdx.x * 256 + threadIdx.x;
    int v = (i < N) ? g_cnt[i] : 0;
    s[threadIdx.x] = v;
    __syncthreads();
    #pragma unroll
    for (int o = 1; o < 256; o <<= 1) {
        int tv = (threadIdx.x >= o) ? s[threadIdx.x - o] : 0;
        __syncthreads();
        s[threadIdx.x] += tv;
        __syncthreads();
    }
    if (i < N) {
        int off = g_boff[blockIdx.x] + s[threadIdx.x] - v;  // exclusive
        g_off[i] = off;
        g_cur[i] = off;
        if (i == N - 1) g_off[N] = off + v;
    }
}

// ---------------------------------------------------------------------------
// place: bucket message records {src, rsqrt(deg_s*deg_d)} by dst
// ---------------------------------------------------------------------------
__global__ void k_place(const void* ei, long long E, int N) {
    long long e = (long long)blockIdx.x * 256 + threadIdx.x;
    long long M = E + (long long)N;
    if (e >= M) return;
    int s, d;
    if (e < E) {
        s = (int)load_edge(ei, e);
        d = (int)load_edge(ei, E + e);
    } else {
        s = d = (int)(e - E);
    }
    float nrm = rsqrtf((float)(g_cnt[s] * g_cnt[d]));
    int pos = atomicAdd(&g_cur[d], 1);
    g_rec[pos] = make_float2(__int_as_float(s), nrm);
}

// ---------------------------------------------------------------------------
// GEMM: out[N,64] = act(X[N,K]) @ W[K,64]; act = relu(x + bias) if RELU_IN.
// CTA tile 128x64, 256 threads, thread tile 8x4, K tiled by 32.
// FFMA2 (fma.rn.f32x2): X stored duplicated (x,x) pairs so LDS.128 yields
// two packed-dup operands; W pairs read via LDS.64 (cols contiguous).
// ---------------------------------------------------------------------------
template <int K, int RELU_IN>
__global__ __launch_bounds__(256, 2)
void k_gemm(const float* __restrict__ X, const float* __restrict__ W,
            const float* __restrict__ bias, float* __restrict__ out, int N) {
    const int KT = 32;
    const int XS = 68;                  // dup row stride (floats): 64 data + 4 pad
    __shared__ float Ws[KT * 64];       // 8 KB
    __shared__ float Xs[128 * XS];      // 34 KB (duplicated X tile)
    __shared__ float bs[64];

    int tid = threadIdx.x;
    int cg = tid & 15;
    int rg = tid >> 4;
    int row0 = blockIdx.x * 128;

    if (RELU_IN && tid < 64) bs[tid] = bias[tid];

    unsigned long long axy[8], azw[8];
    #pragma unroll
    for (int j = 0; j < 8; j++) { axy[j] = 0ull; azw[j] = 0ull; }

    for (int kt = 0; kt < K; kt += KT) {
        __syncthreads();   // also orders bs before first X-tile use
        // load W tile [KT][64]: 512 float4, 2 per thread (contiguous)
        {
            const float4* Wg = (const float4*)W + (long long)kt * 16;
            float4* Wt = (float4*)Ws;
            Wt[tid]       = Wg[tid];
            Wt[tid + 256] = Wg[tid + 256];
        }
        // load X tile [128][KT], store duplicated: (x,x) per value
        #pragma unroll
        for (int i = 0; i < 4; i++) {
            int idx = i * 256 + tid;      // 0..1023
            int r  = idx >> 3;
            int kq = idx & 7;
            int gr = row0 + r;
            float4 v = make_float4(0.f, 0.f, 0.f, 0.f);
            if (gr < N)
                v = *(const float4*)(X + (long long)gr * K + kt + kq * 4);
            if (RELU_IN) {
                int kb = kt + kq * 4;
                v.x = fmaxf(v.x + bs[kb + 0], 0.f);
                v.y = fmaxf(v.y + bs[kb + 1], 0.f);
                v.z = fmaxf(v.z + bs[kb + 2], 0.f);
                v.w = fmaxf(v.w + bs[kb + 3], 0.f);
            }
            float* p = Xs + r * XS + kq * 8;
            *(float2*)(p + 0) = make_float2(v.x, v.x);
            *(float2*)(p + 2) = make_float2(v.y, v.y);
            *(float2*)(p + 4) = make_float2(v.z, v.z);
            *(float2*)(p + 6) = make_float2(v.w, v.w);
        }
        __syncthreads();

        const float* Xr = Xs + (rg * 8) * XS;
        #pragma unroll
        for (int kk = 0; kk < KT / 2; kk++) {   // 2 k-values per iteration
            unsigned long long w0xy = *(const unsigned long long*)(Ws + (2 * kk) * 64 + cg * 4);
            unsigned long long w0zw = *(const unsigned long long*)(Ws + (2 * kk) * 64 + cg * 4 + 2);
            unsigned long long w1xy = *(const unsigned long long*)(Ws + (2 * kk + 1) * 64 + cg * 4);
            unsigned long long w1zw = *(const unsigned long long*)(Ws + (2 * kk + 1) * 64 + cg * 4 + 2);
            #pragma unroll
            for (int j = 0; j < 8; j++) {
                ulonglong2 xd = *(const ulonglong2*)(Xr + j * XS + kk * 4);
                ffma2(axy[j], xd.x, w0xy);
                ffma2(azw[j], xd.x, w0zw);
                ffma2(axy[j], xd.y, w1xy);
                ffma2(azw[j], xd.y, w1zw);
            }
        }
    }

    #pragma unroll
    for (int j = 0; j < 8; j++) {
        int gr = row0 + rg * 8 + j;
        if (gr < N) {
            float2 lo = *(float2*)&axy[j];
            float2 hi = *(float2*)&azw[j];
            ((float4*)(out + (long long)gr * 64))[cg] =
                make_float4(lo.x, lo.y, hi.x, hi.y);
        }
    }
}

// ---------------------------------------------------------------------------
// Aggregate: out[n] = sum over CSR bucket of h[src]*norm.  Warp per node;
// lanes 0-15 / 16-31 process alternating records, chunk k = lane&15.
// EPI==1: fuse +b2 and log_softmax, write final output.
// ---------------------------------------------------------------------------
template <int EPI>
__global__ void k_agg(const float* __restrict__ h, float* __restrict__ out,
                      const float* __restrict__ bias, int N) {
    int node = blockIdx.x * 8 + (threadIdx.x >> 5);
    if (node >= N) return;
    int lane = threadIdx.x & 31;
    int k = lane & 15;
    int half = lane >> 4;
    int beg = g_off[node];
    int end = g_off[node + 1];

    float4 acc = make_float4(0.f, 0.f, 0.f, 0.f);
    #pragma unroll 2
    for (int j = beg + half; j < end; j += 2) {
        float2 r = g_rec[j];
        int s = __float_as_int(r.x);
        float4 v = __ldg((const float4*)(h + (long long)s * 64) + k);
        acc.x += v.x * r.y;
        acc.y += v.y * r.y;
        acc.z += v.z * r.y;
        acc.w += v.w * r.y;
    }
    // combine the two halves (per-k sums end up duplicated in both halves)
    acc.x += __shfl_xor_sync(0xffffffffu, acc.x, 16);
    acc.y += __shfl_xor_sync(0xffffffffu, acc.y, 16);
    acc.z += __shfl_xor_sync(0xffffffffu, acc.z, 16);
    acc.w += __shfl_xor_sync(0xffffffffu, acc.w, 16);

    if (EPI == 0) {
        if (half == 0)
            ((float4*)(out + (long long)node * 64))[k] = acc;
    } else {
        float4 b = ((const float4*)bias)[k];
        acc.x += b.x; acc.y += b.y; acc.z += b.z; acc.w += b.w;
        float m = fmaxf(fmaxf(acc.x, acc.y), fmaxf(acc.z, acc.w));
        #pragma unroll
        for (int o = 16; o > 0; o >>= 1)
            m = fmaxf(m, __shfl_xor_sync(0xffffffffu, m, o));
        float s = expf(acc.x - m) + expf(acc.y - m) + expf(acc.z - m) + expf(acc.w - m);
        #pragma unroll
        for (int o = 16; o > 0; o >>= 1)
            s += __shfl_xor_sync(0xffffffffu, s, o);
        // 32-lane sum double-counts (k duplicated across halves) -> halve
        float lse = m + logf(s * 0.5f);
        if (half == 0) {
            float4 r = make_float4(acc.x - lse, acc.y - lse, acc.z - lse, acc.w - lse);
            ((float4*)(out + (long long)node * 64))[k] = r;
        }
    }
}

// ---------------------------------------------------------------------------
extern "C" void kernel_launch(void* const* d_in, const int* in_sizes, int n_in,
                              void* d_out, int out_size) {
    const float* x  = (const float*)d_in[0];
    const void*  ei = d_in[1];
    const float* W1 = (const float*)d_in[2];
    const float* b1 = (const float*)d_in[3];
    const float* W2 = (const float*)d_in[4];
    const float* b2 = (const float*)d_in[5];
    float* out = (float*)d_out;

    int N = in_sizes[0] / 128;                 // 100000
    long long E = (long long)in_sizes[1] / 2;  // 1600000
    long long M = E + (long long)N;

    // One-time host-side resources (no device memory involved). The captured
    // work is identical on every call.
    static cudaStream_t s2 = nullptr;
    static cudaEvent_t evFork = nullptr, evJoin = nullptr;
    if (!s2) {
        cudaStreamCreateWithFlags(&s2, cudaStreamNonBlocking);
        cudaEventCreateWithFlags(&evFork, cudaEventDisableTiming);
        cudaEventCreateWithFlags(&evJoin, cudaEventDisableTiming);
    }

    float *ph, *pagg;
    cudaGetSymbolAddress((void**)&ph, g_h);
    cudaGetSymbolAddress((void**)&pagg, g_agg);

    int bN    = (N + 255) / 256;
    int bDeg  = (int)((E + 255) / 256);
    int bMsg  = (int)((M + 255) / 256);
    int bGemm = (N + 127) / 128;
    int bAgg  = (N + 7) / 8;

    // Fork: GEMM1 (x,W1 only) runs on s2, concurrent with CSR prep on the
    // capture (default) stream.
    cudaEventRecord(evFork, 0);
    cudaStreamWaitEvent(s2, evFork, 0);
    k_gemm<128, 0><<<bGemm, 256, 0, s2>>>(x, W1, nullptr, ph, N);
    cudaEventRecord(evJoin, s2);

    k_init<<<bN, 256>>>(ei, N);
    k_count<<<bDeg, 256>>>(ei, E);
    k_scan1<<<bN, 256>>>(N);
    k_scan2<<<1, 512>>>(bN);
    k_scan3<<<bN, 256>>>(N);
    k_place<<<bMsg, 256>>>(ei, E, N);

    // Join: aggregation needs both g_h (s2) and g_rec (default)
    cudaStreamWaitEvent(0, evJoin, 0);

    // layer 1 aggregate
    k_agg<0><<<bAgg, 256>>>(ph, pagg, nullptr, N);

    // layer 2: h2 = relu(agg1 + b1) @ W2 ; out = log_softmax(aggregate(h2) + b2)
    k_gemm<64, 1><<<bGemm, 256>>>(pagg, W2, b1, ph, N);
    k_agg<1><<<bAgg, 256>>>(ph, out, b2, N);
}

// round 5
// speedup vs baseline: 3.4594x; 1.0264x over previous
#include <cuda_runtime.h>
#include <cuda_bf16.h>
#include <math.h>

// Fixed problem shape (from setup_inputs): N=100000, E=1600000, F_IN=128, H=C=64
#define NNODES 100000
#define HD 64
#define MSGMAX 1800000   // E + N with headroom

// Scratch (allocation-free: __device__ globals)
__device__ int    g_cnt[NNODES];            // per-dst message count (incl. self-loop)
__device__ int    g_off[NNODES + 1];        // CSR offsets
__device__ int    g_cur[NNODES];            // placement cursors
__device__ int    g_bsum[512];              // block sums for scan
__device__ int    g_boff[512];              // block offsets for scan
__device__ float2 g_rec[MSGMAX];            // per-message {src_bits, norm}
__device__ uint4  g_h[NNODES * 8];          // GEMM output in bf16 (64 bf16 = 8 uint4/row)
__device__ float  g_agg[NNODES * HD];       // layer-1 aggregate (fp32)
__device__ int    g_is64;                   // edge_index dtype flag

__device__ __forceinline__ long long load_edge(const void* ei, long long pos) {
    if (g_is64) return ((const long long*)ei)[pos];
    return (long long)((const int*)ei)[pos];
}

__device__ __forceinline__ void ffma2(unsigned long long& d, unsigned long long a,
                                      unsigned long long b) {
    asm("fma.rn.f32x2 %0, %1, %2, %0;" : "+l"(d) : "l"(a), "l"(b));
}

// ---------------------------------------------------------------------------
// init: cnt = 1 (self loop), detect index width
// ---------------------------------------------------------------------------
__global__ void k_init(const void* ei, int N) {
    int i = blockIdx.x * 256 + threadIdx.x;
    if (i < N) g_cnt[i] = 1;
    if (i == 0) {
        const unsigned long long* p = (const unsigned long long*)ei;
        int ok = 1;
        #pragma unroll 4
        for (int j = 0; j < 64; j++)
            if (p[j] >= (unsigned long long)N) ok = 0;
        g_is64 = ok;
    }
}

// ---------------------------------------------------------------------------
// degree count over dst
// ---------------------------------------------------------------------------
__global__ void k_count(const void* ei, long long E) {
    long long e = (long long)blockIdx.x * 256 + threadIdx.x;
    if (e < E) {
        int d = (int)load_edge(ei, E + e);
        atomicAdd(&g_cnt[d], 1);
    }
}

// ---------------------------------------------------------------------------
// 3-phase exclusive scan of g_cnt -> g_off  (N <= 131072: <=512 blocks of 256)
// ---------------------------------------------------------------------------
__global__ void k_scan1(int N) {
    __shared__ int s[256];
    int i = blockIdx.x * 256 + threadIdx.x;
    int v = (i < N) ? g_cnt[i] : 0;
    s[threadIdx.x] = v;
    __syncthreads();
    #pragma unroll
    for (int o = 128; o > 0; o >>= 1) {
        if (threadIdx.x < o) s[threadIdx.x] += s[threadIdx.x + o];
        __syncthreads();
    }
    if (threadIdx.x == 0) g_bsum[blockIdx.x] = s[0];
}

// warp-shuffle scan of up to 512 block sums (16 warps)
__global__ void k_scan2(int nb) {
    __shared__ int wsum[16];
    int t = threadIdx.x;
    int lane = t & 31;
    int w = t >> 5;
    int v = (t < nb) ? g_bsum[t] : 0;
    int x = v;
    #pragma unroll
    for (int o = 1; o < 32; o <<= 1) {
        int y = __shfl_up_sync(0xffffffffu, x, o);
        if (lane >= o) x += y;
    }
    if (lane == 31) wsum[w] = x;
    __syncthreads();
    if (w == 0) {
        int ws = (lane < 16) ? wsum[lane] : 0;
        #pragma unroll
        for (int o = 1; o < 16; o <<= 1) {
            int y = __shfl_up_sync(0xffffffffu, ws, o);
            if (lane >= o) ws += y;
        }
        if (lane < 16) wsum[lane] = ws;
    }
    __syncthreads();
    int base = (w > 0) ? wsum[w - 1] : 0;
    if (t < nb) g_boff[t] = base + x - v;   // exclusive
}

__global__ void k_scan3(int N) {
    __shared__ int s[256];
    int i = blockIdx.x * 256 + threadIdx.x;
    int v = (i < N) ? g_cnt[i] : 0;
    s[threadIdx.x] = v;
    __syncthreads();
    #pragma unroll
    for (int o = 1; o < 256; o <<= 1) {
        int tv = (threadIdx.x >= o) ? s[threadIdx.x - o] : 0;
        __syncthreads();
        s[threadIdx.x] += tv;
        __syncthreads();
    }
    if (i < N) {
        int off = g_boff[blockIdx.x] + s[threadIdx.x] - v;  // exclusive
        g_off[i] = off;
        g_cur[i] = off;
        if (i == N - 1) g_off[N] = off + v;
    }
}

// ---------------------------------------------------------------------------
// place: bucket message records {src, rsqrt(deg_s*deg_d)} by dst
// ---------------------------------------------------------------------------
__global__ void k_place(const void* ei, long long E, int N) {
    long long e = (long long)blockIdx.x * 256 + threadIdx.x;
    long long M = E + (long long)N;
    if (e >= M) return;
    int s, d;
    if (e < E) {
        s = (int)load_edge(ei, e);
        d = (int)load_edge(ei, E + e);
    } else {
        s = d = (int)(e - E);
    }
    float nrm = rsqrtf((float)(g_cnt[s] * g_cnt[d]));
    int pos = atomicAdd(&g_cur[d], 1);
    g_rec[pos] = make_float2(__int_as_float(s), nrm);
}

// ---------------------------------------------------------------------------
// GEMM: out[N,64](bf16) = act(X[N,K]) @ W[K,64]; act = relu(x+bias) if RELU_IN.
// CTA tile 128x64, 256 threads, thread tile 8x4, K tiled by 32, FFMA2 core.
// fp32 accumulate; bf16 rounding only at the final store.
// ---------------------------------------------------------------------------
template <int K, int RELU_IN>
__global__ __launch_bounds__(256, 2)
void k_gemm(const float* __restrict__ X, const float* __restrict__ W,
            const float* __restrict__ bias, uint2* __restrict__ out, int N) {
    const int KT = 32;
    const int XS = 68;                  // dup row stride (floats): 64 data + 4 pad
    __shared__ float Ws[KT * 64];       // 8 KB
    __shared__ float Xs[128 * XS];      // 34 KB (duplicated X tile)
    __shared__ float bs[64];

    int tid = threadIdx.x;
    int cg = tid & 15;
    int rg = tid >> 4;
    int row0 = blockIdx.x * 128;

    if (RELU_IN && tid < 64) bs[tid] = bias[tid];

    unsigned long long axy[8], azw[8];
    #pragma unroll
    for (int j = 0; j < 8; j++) { axy[j] = 0ull; azw[j] = 0ull; }

    for (int kt = 0; kt < K; kt += KT) {
        __syncthreads();   // also orders bs before first X-tile use
        {
            const float4* Wg = (const float4*)W + (long long)kt * 16;
            float4* Wt = (float4*)Ws;
            Wt[tid]       = Wg[tid];
            Wt[tid + 256] = Wg[tid + 256];
        }
        #pragma unroll
        for (int i = 0; i < 4; i++) {
            int idx = i * 256 + tid;      // 0..1023
            int r  = idx >> 3;
            int kq = idx & 7;
            int gr = row0 + r;
            float4 v = make_float4(0.f, 0.f, 0.f, 0.f);
            if (gr < N)
                v = *(const float4*)(X + (long long)gr * K + kt + kq * 4);
            if (RELU_IN) {
                int kb = kt + kq * 4;
                v.x = fmaxf(v.x + bs[kb + 0], 0.f);
                v.y = fmaxf(v.y + bs[kb + 1], 0.f);
                v.z = fmaxf(v.z + bs[kb + 2], 0.f);
                v.w = fmaxf(v.w + bs[kb + 3], 0.f);
            }
            float* p = Xs + r * XS + kq * 8;
            *(float2*)(p + 0) = make_float2(v.x, v.x);
            *(float2*)(p + 2) = make_float2(v.y, v.y);
            *(float2*)(p + 4) = make_float2(v.z, v.z);
            *(float2*)(p + 6) = make_float2(v.w, v.w);
        }
        __syncthreads();

        const float* Xr = Xs + (rg * 8) * XS;
        #pragma unroll
        for (int kk = 0; kk < KT / 2; kk++) {   // 2 k-values per iteration
            unsigned long long w0xy = *(const unsigned long long*)(Ws + (2 * kk) * 64 + cg * 4);
            unsigned long long w0zw = *(const unsigned long long*)(Ws + (2 * kk) * 64 + cg * 4 + 2);
            unsigned long long w1xy = *(const unsigned long long*)(Ws + (2 * kk + 1) * 64 + cg * 4);
            unsigned long long w1zw = *(const unsigned long long*)(Ws + (2 * kk + 1) * 64 + cg * 4 + 2);
            #pragma unroll
            for (int j = 0; j < 8; j++) {
                ulonglong2 xd = *(const ulonglong2*)(Xr + j * XS + kk * 4);
                ffma2(axy[j], xd.x, w0xy);
                ffma2(azw[j], xd.x, w0zw);
                ffma2(axy[j], xd.y, w1xy);
                ffma2(azw[j], xd.y, w1zw);
            }
        }
    }

    #pragma unroll
    for (int j = 0; j < 8; j++) {
        int gr = row0 + rg * 8 + j;
        if (gr < N) {
            float2 lo = *(float2*)&axy[j];
            float2 hi = *(float2*)&azw[j];
            __nv_bfloat162 b0 = __float22bfloat162_rn(lo);
            __nv_bfloat162 b1 = __float22bfloat162_rn(hi);
            uint2 pk;
            pk.x = *(unsigned*)&b0;
            pk.y = *(unsigned*)&b1;
            out[(long long)gr * 16 + cg] = pk;   // row = 16 uint2 (64 bf16)
        }
    }
}

// ---------------------------------------------------------------------------
// Aggregate from bf16 h: out[n] = sum over CSR bucket of h[src]*norm.
// Warp per node; 4 groups of 8 lanes, each group one record, lane gl owns
// 16B (8 bf16 features). fp32 accumulate, shfl-combine groups.
// EPI==1: fuse +b2 and log_softmax, write final output.
// ---------------------------------------------------------------------------
template <int EPI>
__global__ void k_agg(const uint4* __restrict__ h, float* __restrict__ out,
                      const float* __restrict__ bias, int N) {
    int node = blockIdx.x * 8 + (threadIdx.x >> 5);
    if (node >= N) return;
    int lane = threadIdx.x & 31;
    int grp = lane >> 3;     // record slot 0..3
    int gl  = lane & 7;      // 16B chunk within row
    int beg = g_off[node];
    int end = g_off[node + 1];

    float2 acc[4];
    #pragma unroll
    for (int i = 0; i < 4; i++) acc[i] = make_float2(0.f, 0.f);

    #pragma unroll 2
    for (int j = beg + grp; j < end; j += 4) {
        float2 r = g_rec[j];
        int s = __float_as_int(r.x);
        uint4 v = __ldg(h + (long long)s * 8 + gl);
        float2 f;
        f = __bfloat1622float2(*(__nv_bfloat162*)&v.x);
        acc[0].x += f.x * r.y; acc[0].y += f.y * r.y;
        f = __bfloat1622float2(*(__nv_bfloat162*)&v.y);
        acc[1].x += f.x * r.y; acc[1].y += f.y * r.y;
        f = __bfloat1622float2(*(__nv_bfloat162*)&v.z);
        acc[2].x += f.x * r.y; acc[2].y += f.y * r.y;
        f = __bfloat1622float2(*(__nv_bfloat162*)&v.w);
        acc[3].x += f.x * r.y; acc[3].y += f.y * r.y;
    }
    // combine the 4 record-groups (lanes with equal gl)
    #pragma unroll
    for (int i = 0; i < 4; i++) {
        acc[i].x += __shfl_xor_sync(0xffffffffu, acc[i].x, 8);
        acc[i].y += __shfl_xor_sync(0xffffffffu, acc[i].y, 8);
        acc[i].x += __shfl_xor_sync(0xffffffffu, acc[i].x, 16);
        acc[i].y += __shfl_xor_sync(0xffffffffu, acc[i].y, 16);
    }

    if (EPI == 0) {
        if (lane < 8) {
            float4* op = (float4*)(out + (long long)node * 64 + gl * 8);
            op[0] = make_float4(acc[0].x, acc[0].y, acc[1].x, acc[1].y);
            op[1] = make_float4(acc[2].x, acc[2].y, acc[3].x, acc[3].y);
        }
    } else {
        const float4* bp = (const float4*)(bias + gl * 8);
        float4 b0 = bp[0], b1 = bp[1];
        acc[0].x += b0.x; acc[0].y += b0.y; acc[1].x += b0.z; acc[1].y += b0.w;
        acc[2].x += b1.x; acc[2].y += b1.y; acc[3].x += b1.z; acc[3].y += b1.w;
        float m = fmaxf(fmaxf(fmaxf(acc[0].x, acc[0].y), fmaxf(acc[1].x, acc[1].y)),
                        fmaxf(fmaxf(acc[2].x, acc[2].y), fmaxf(acc[3].x, acc[3].y)));
        #pragma unroll
        for (int o = 1; o < 8; o <<= 1)
            m = fmaxf(m, __shfl_xor_sync(0xffffffffu, m, o));
        float s = expf(acc[0].x - m) + expf(acc[0].y - m)
                + expf(acc[1].x - m) + expf(acc[1].y - m)
                + expf(acc[2].x - m) + expf(acc[2].y - m)
                + expf(acc[3].x - m) + expf(acc[3].y - m);
        #pragma unroll
        for (int o = 1; o < 8; o <<= 1)
            s += __shfl_xor_sync(0xffffffffu, s, o);
        float lse = m + logf(s);
        if (lane < 8) {
            float4* op = (float4*)(out + (long long)node * 64 + gl * 8);
            op[0] = make_float4(acc[0].x - lse, acc[0].y - lse,
                                acc[1].x - lse, acc[1].y - lse);
            op[1] = make_float4(acc[2].x - lse, acc[2].y - lse,
                                acc[3].x - lse, acc[3].y - lse);
        }
    }
}

// ---------------------------------------------------------------------------
extern "C" void kernel_launch(void* const* d_in, const int* in_sizes, int n_in,
                              void* d_out, int out_size) {
    const float* x  = (const float*)d_in[0];
    const void*  ei = d_in[1];
    const float* W1 = (const float*)d_in[2];
    const float* b1 = (const float*)d_in[3];
    const float* W2 = (const float*)d_in[4];
    const float* b2 = (const float*)d_in[5];
    float* out = (float*)d_out;

    int N = in_sizes[0] / 128;                 // 100000
    long long E = (long long)in_sizes[1] / 2;  // 1600000
    long long M = E + (long long)N;

    static cudaStream_t s2 = nullptr;
    static cudaEvent_t evFork = nullptr, evJoin = nullptr;
    if (!s2) {
        cudaStreamCreateWithFlags(&s2, cudaStreamNonBlocking);
        cudaEventCreateWithFlags(&evFork, cudaEventDisableTiming);
        cudaEventCreateWithFlags(&evJoin, cudaEventDisableTiming);
    }

    uint4* ph;
    float* pagg;
    cudaGetSymbolAddress((void**)&ph, g_h);
    cudaGetSymbolAddress((void**)&pagg, g_agg);

    int bN    = (N + 255) / 256;
    int bDeg  = (int)((E + 255) / 256);
    int bMsg  = (int)((M + 255) / 256);
    int bGemm = (N + 127) / 128;
    int bAgg  = (N + 7) / 8;

    // Fork: GEMM1 (x,W1 only) on s2, concurrent with CSR prep on capture stream.
    cudaEventRecord(evFork, 0);
    cudaStreamWaitEvent(s2, evFork, 0);
    k_gemm<128, 0><<<bGemm, 256, 0, s2>>>(x, W1, nullptr, (uint2*)ph, N);
    cudaEventRecord(evJoin, s2);

    k_init<<<bN, 256>>>(ei, N);
    k_count<<<bDeg, 256>>>(ei, E);
    k_scan1<<<bN, 256>>>(N);
    k_scan2<<<1, 512>>>(bN);
    k_scan3<<<bN, 256>>>(N);
    k_place<<<bMsg, 256>>>(ei, E, N);

    // Join: aggregation needs both g_h (s2) and g_rec (default)
    cudaStreamWaitEvent(0, evJoin, 0);

    // layer 1 aggregate (fp32 out)
    k_agg<0><<<bAgg, 256>>>(ph, pagg, nullptr, N);

    // layer 2: h2 = relu(agg1 + b1) @ W2 (bf16 out); out = log_softmax(agg + b2)
    k_gemm<64, 1><<<bGemm, 256>>>(pagg, W2, b1, (uint2*)ph, N);
    k_agg<1><<<bAgg, 256>>>(ph, out, b2, N);
}